// round 16
// baseline (speedup 1.0000x reference)
#include <cuda_runtime.h>
#include <cuda_bf16.h>
#include <mma.h>

using namespace nvcuda;

// ---------------------------------------------------------------------------
// NeuralODEFlow: z' = mlp(z), Euler, log_det via finite-difference trace.
//   trace_step = dt/H * (Sy_new - Sy_old)  +  dt * m1^T Q m2
// with Q[k,i] = W2[k,i]*(W3@W1)[i,k], m1/m2 = ReLU masks at z_new.
//
// R15: single persistent kernel (128 CTAs x 256 thr, 187KB smem, 1 CTA/SM,
// all co-resident). W1 staged into smem ONCE. Software grid barrier between
// phases. Phase A = R14 k1 body; Phase B = R14 warp-specialized k2 body
// (FFMA warps 0-3: u2 fp32; HMMA warps 4-7: V bf16). Prologue = Qb init;
// epilogue = final logdet + z copy. One launch total.
// ---------------------------------------------------------------------------

#define BATCH 1024
#define DIM   64
#define HID   512
#define NSTEP 9
#define HSTEP 1e-5f
#define GRID  128

// scratch (device globals: allocation-free)
__device__ __nv_bfloat16 g_Qb[HID * HID];
__device__ float g_z[BATCH * DIM];
__device__ float g_h1[BATCH * HID];
__device__ float g_ypart[BATCH * 8 * DIM];   // [row][cb][j]
__device__ float g_part [BATCH * 8];         // bilinear partials
__device__ float g_ysump[BATCH * 8];         // rowsum-of-y partials (excl. b3)
__device__ float g_ysum[2][BATCH];           // Sy per eval (ping-pong)

// software grid barrier (sense-reversing generation counter)
__device__ unsigned g_bar_cnt;
__device__ volatile unsigned g_bar_gen;

__device__ __forceinline__ void grid_sync() {
    __syncthreads();
    if (threadIdx.x == 0) {
        __threadfence();                       // release prior writes
        unsigned gen = g_bar_gen;              // MUST read before arriving
        if (atomicAdd(&g_bar_cnt, 1u) == GRID - 1u) {
            g_bar_cnt = 0u;
            __threadfence();
            g_bar_gen = gen + 1u;
        } else {
            while (g_bar_gen == gen) { }
            __threadfence();                   // acquire
        }
    }
    __syncthreads();
}

struct Dts { float tt[NSTEP + 1]; };

// phase-B smem macros (sm = k2 region pointer)
#define ASMS(k_, r_) sm[(k_) * 64 + (r_)]
#define BS1(k_, c_)  sm[1024 + (k_) * 64 + (c_)]
#define VBUF(r_, c_) sm[(r_) * 68 + (c_)]
#define H2S(r_, c_)  sm[4352 + (r_) * 68 + (c_)]
#define W3S(k_, j_)  sm[8704 + (k_) * 68 + (j_)]
#define RED(x_, y_)  sm[13056 + (x_) * 64 + (y_)]

__global__ __launch_bounds__(256) void k_mega(
    const float* __restrict__ xin, const float* __restrict__ W1,
    const float* __restrict__ b1,  const float* __restrict__ W2,
    const float* __restrict__ b2,  const float* __restrict__ W3,
    const float* __restrict__ b3,  float* __restrict__ out, Dts dts) {
    extern __shared__ float dsm[];
    float* W1s = dsm;                    // [64][512] = 32768 floats (persists)
    float* sm  = dsm + DIM * HID;        // k2 region: 14080 floats
    const int bid = blockIdx.x;
    const int t = threadIdx.x;
    float* out_logdet = out + BATCH * DIM;

    // ======================= prologue =======================
    // stage W1 -> smem (once for the whole run)
    {
        const float4* src = (const float4*)W1;
        float4* dst = (float4*)W1s;
#pragma unroll
        for (int q = 0; q < 32; ++q) dst[t + 256 * q] = src[t + 256 * q];
    }
    // CTAs 0..63: Qb[k,i] = bf16( W2[k,i] * (W3@W1)[i,k] )
    if (bid < 64) {
        float* w3t = sm;             // [64][68]
        float* w1s = sm + 4352;      // [64][64]
        int i0 = (bid & 7) * 64, k0 = (bid >> 3) * 64;
#pragma unroll
        for (int q = 0; q < 16; ++q) {
            int e = t + 256 * q;
            int hi = e >> 6, lo = e & 63;
            w3t[lo * 68 + hi] = W3[(i0 + hi) * DIM + lo];
            w1s[hi * 64 + lo] = W1[hi * HID + k0 + lo];
        }
        __syncthreads();
        int tx = t & 15, ty = t >> 4;
        float acc[4][4];
#pragma unroll
        for (int r = 0; r < 4; ++r)
#pragma unroll
            for (int c = 0; c < 4; ++c) acc[r][c] = 0.f;
#pragma unroll 4
        for (int j = 0; j < 64; ++j) {
            float a[4], b[4];
            *(float4*)a = *(const float4*)&w3t[j * 68 + tx * 4];
            *(float4*)b = *(const float4*)&w1s[j * 64 + ty * 4];
#pragma unroll
            for (int r = 0; r < 4; ++r)
#pragma unroll
                for (int c = 0; c < 4; ++c) acc[r][c] += b[r] * a[c];
        }
#pragma unroll
        for (int r = 0; r < 4; ++r) {
            int idx = (k0 + ty * 4 + r) * HID + i0 + tx * 4;
            float4 w2v = *(const float4*)&W2[idx];
            __nv_bfloat162 q01 = __floats2bfloat162_rn(w2v.x * acc[r][0], w2v.y * acc[r][1]);
            __nv_bfloat162 q23 = __floats2bfloat162_rn(w2v.z * acc[r][2], w2v.w * acc[r][3]);
            *(__nv_bfloat162*)&g_Qb[idx]     = q01;
            *(__nv_bfloat162*)&g_Qb[idx + 2] = q23;
        }
        if (bid == 0) {
            for (int i = t; i < BATCH; i += 256) out_logdet[i] = 0.f;
        }
    }
    grid_sync();

    // ======================= evals 0..NSTEP =======================
#pragma unroll 1
    for (int e = 0; e <= NSTEP; ++e) {
        float dt     = (e >= 1) ? (dts.tt[e] - dts.tt[e - 1]) : 0.f;
        float dtPrev = (e >= 2) ? (dts.tt[e - 1] - dts.tt[e - 2]) : 0.f;

        // -------- phase A: bookkeeping + z Euler update + layer1 --------
        {
            float* zs = sm;              // [8][64]
            int row0 = bid * 8;

            if (e > 0 && t < 8) {
                int row = row0 + t;
                float sy = 0.f, bl = 0.f;
#pragma unroll
                for (int cbk = 0; cbk < 8; ++cbk) {
                    sy += g_ysump[row * 8 + cbk];
                    bl += g_part [row * 8 + cbk];
                }
                if (e >= 2) {
                    float tr = (sy - g_ysum[(e - 2) & 1][row]) * (dtPrev / HSTEP)
                             + bl * dtPrev;
                    out_logdet[row] -= tr;
                }
                g_ysum[(e - 1) & 1][row] = sy;
            }

#pragma unroll
            for (int q = 0; q < 2; ++q) {
                int idx = t + 256 * q;               // 0..511
                int g = row0 * DIM + idx;
                float z;
                if (e == 0) {
                    z = xin[g];
                } else {
                    int row = row0 + (idx >> 6), j = idx & 63;
                    float s = 0.f;
#pragma unroll
                    for (int cbk = 0; cbk < 8; ++cbk)
                        s += g_ypart[(row * 8 + cbk) * DIM + j];
                    z = g_z[g] + dt * (s + b3[j]);
                }
                zs[idx] = z;
                g_z[g] = z;
            }
            __syncthreads();

            float acc0[8], acc1[8];
#pragma unroll
            for (int r = 0; r < 8; ++r) { acc0[r] = 0.f; acc1[r] = 0.f; }
            int c0 = t, c1 = t + 256;
#pragma unroll 8
            for (int k = 0; k < 64; ++k) {
                float wa = W1s[k * HID + c0];
                float wb = W1s[k * HID + c1];
#pragma unroll
                for (int r = 0; r < 8; ++r) {
                    float z = zs[r * 64 + k];
                    acc0[r] += z * wa;
                    acc1[r] += z * wb;
                }
            }
            float ba = b1[c0], bb = b1[c1];
#pragma unroll
            for (int r = 0; r < 8; ++r) {
                g_h1[(row0 + r) * HID + c0] = fmaxf(acc0[r] + ba, 0.f);
                g_h1[(row0 + r) * HID + c1] = fmaxf(acc1[r] + bb, 0.f);
            }
        }
        grid_sync();

        // -------- phase B: warp-specialized dual GEMM + fused layer3 --------
        {
            __nv_bfloat16* amask = (__nv_bfloat16*)(sm + 2048);   // [64][16]
            __nv_bfloat16* qbs   = (__nv_bfloat16*)(sm + 2560);   // [16][64]
            int cb = bid & 7, rb = bid >> 3;
            int row0 = rb * 64, col0 = cb * 64;
            int wid = t >> 5;

            int tx = t & 15, ty = (t >> 4) & 7;
            float au[8][4];
#pragma unroll
            for (int r = 0; r < 8; ++r)
#pragma unroll
                for (int c = 0; c < 4; ++c) au[r][c] = 0.f;

            wmma::fragment<wmma::matrix_a, 16, 16, 16, __nv_bfloat16, wmma::row_major> fa;
            wmma::fragment<wmma::matrix_b, 16, 16, 16, __nv_bfloat16, wmma::row_major> fb;
            wmma::fragment<wmma::accumulator, 16, 16, 16, float> fcv[4];
#pragma unroll
            for (int c = 0; c < 4; ++c) wmma::fill_fragment(fcv[c], 0.f);

            int ar = t >> 2, ak = (t & 3) * 4;
            int bk = t >> 4, bc = (t & 15) * 4;

            const __nv_bfloat16 bONE  = __float2bfloat16(1.f);
            const __nv_bfloat16 bZERO = __float2bfloat16(0.f);

            for (int k0 = 0; k0 < HID; k0 += 16) {
                float4 a4 = *(const float4*)&g_h1[(row0 + ar) * HID + k0 + ak];
                ASMS(ak + 0, ar) = a4.x; ASMS(ak + 1, ar) = a4.y;
                ASMS(ak + 2, ar) = a4.z; ASMS(ak + 3, ar) = a4.w;
                *(__nv_bfloat162*)&amask[ar * 16 + ak] =
                    __halves2bfloat162(a4.x > 0.f ? bONE : bZERO, a4.y > 0.f ? bONE : bZERO);
                *(__nv_bfloat162*)&amask[ar * 16 + ak + 2] =
                    __halves2bfloat162(a4.z > 0.f ? bONE : bZERO, a4.w > 0.f ? bONE : bZERO);
                *(float4*)&BS1(bk, bc) = *(const float4*)&W2[(k0 + bk) * HID + col0 + bc];
                *(uint2*)&qbs[bk * 64 + bc] = *(const uint2*)&g_Qb[(k0 + bk) * HID + col0 + bc];
                __syncthreads();

                if (wid < 4) {
#pragma unroll
                    for (int kk = 0; kk < 16; ++kk) {
                        float a[8], w[4];
                        *(float4*)&a[0] = *(const float4*)&ASMS(kk, ty * 8);
                        *(float4*)&a[4] = *(const float4*)&ASMS(kk, ty * 8 + 4);
                        *(float4*)w = *(const float4*)&BS1(kk, tx * 4);
#pragma unroll
                        for (int r = 0; r < 8; ++r)
#pragma unroll
                            for (int c = 0; c < 4; ++c) au[r][c] += a[r] * w[c];
                    }
                } else {
                    int v = wid - 4;
                    wmma::load_matrix_sync(fa, amask + v * 16 * 16, 16);
#pragma unroll
                    for (int c = 0; c < 4; ++c) {
                        wmma::load_matrix_sync(fb, qbs + c * 16, 64);
                        wmma::mma_sync(fcv[c], fa, fb, fcv[c]);
                    }
                }
                __syncthreads();
            }

            // V fragments -> VBUF; W3 tile -> W3S
            if (wid >= 4) {
                int v = wid - 4;
#pragma unroll
                for (int c = 0; c < 4; ++c)
                    wmma::store_matrix_sync(&VBUF(v * 16, c * 16), fcv[c], 68,
                                            wmma::mem_row_major);
            }
#pragma unroll
            for (int q = 0; q < 4; ++q) {
                int f = t + 256 * q;
                int k = f >> 4, j4 = (f & 15) * 4;
                *(float4*)&W3S(k, j4) = *(const float4*)&W3[(col0 + k) * DIM + j4];
            }
            __syncthreads();

            if (wid < 4) {
                float b2v[4];
                *(float4*)b2v = *(const float4*)&b2[col0 + tx * 4];
#pragma unroll
                for (int r = 0; r < 8; ++r) {
                    float av4[4];
                    *(float4*)av4 = *(const float4*)&VBUF(ty * 8 + r, tx * 4);
                    float h2v[4];
                    float s = 0.f;
#pragma unroll
                    for (int c = 0; c < 4; ++c) {
                        float u = au[r][c] + b2v[c];
                        h2v[c] = fmaxf(u, 0.f);
                        s += (u > 0.f) ? av4[c] : 0.f;
                    }
                    *(float4*)&H2S(ty * 8 + r, tx * 4) = *(float4*)h2v;
                    RED(tx, ty * 8 + r) = s;
                }
            }
            __syncthreads();

            // ypart = h2_tile @ W3_tile (all 256 threads, 4x4 each)
            int tx2 = t & 15, ty2 = t >> 4;
            float ay[4][4];
#pragma unroll
            for (int r = 0; r < 4; ++r)
#pragma unroll
                for (int c = 0; c < 4; ++c) ay[r][c] = 0.f;

#pragma unroll 8
            for (int k = 0; k < 64; ++k) {
                float a[4], w[4];
#pragma unroll
                for (int r = 0; r < 4; ++r) a[r] = H2S(ty2 * 4 + r, k);
                *(float4*)w = *(const float4*)&W3S(k, tx2 * 4);
#pragma unroll
                for (int r = 0; r < 4; ++r)
#pragma unroll
                    for (int c = 0; c < 4; ++c) ay[r][c] += a[r] * w[c];
            }
#pragma unroll
            for (int r = 0; r < 4; ++r) {
                int row = row0 + ty2 * 4 + r;
                *(float4*)&g_ypart[(row * 8 + cb) * DIM + tx2 * 4] = *(float4*)ay[r];
            }

            if (t < 64) {
                float s = 0.f;
#pragma unroll
                for (int xx = 0; xx < 16; ++xx) s += RED(xx, t);
                g_part[(row0 + t) * 8 + cb] = s;
            }
            __syncthreads();

#pragma unroll
            for (int r = 0; r < 4; ++r)
                RED(tx2, ty2 * 4 + r) = ay[r][0] + ay[r][1] + ay[r][2] + ay[r][3];
            __syncthreads();
            if (t < 64) {
                float s = 0.f;
#pragma unroll
                for (int xx = 0; xx < 16; ++xx) s += RED(xx, t);
                g_ysump[(row0 + t) * 8 + cb] = s;
            }
        }
        grid_sync();
    }

    // ======================= epilogue =======================
    {
        int row0 = bid * 8;
        if (t < 8) {
            int row = row0 + t;
            float sy = 0.f, bl = 0.f;
#pragma unroll
            for (int cbk = 0; cbk < 8; ++cbk) {
                sy += g_ysump[row * 8 + cbk];
                bl += g_part [row * 8 + cbk];
            }
            float dtL = dts.tt[NSTEP] - dts.tt[NSTEP - 1];
            float tr = (sy - g_ysum[(NSTEP - 1) & 1][row]) * (dtL / HSTEP) + bl * dtL;
            out_logdet[row] -= tr;
        }
#pragma unroll
        for (int q = 0; q < 2; ++q) {
            int idx = t + 256 * q;
            out[row0 * DIM + idx] = g_z[row0 * DIM + idx];
        }
    }
}

// ---------------------------------------------------------------------------
extern "C" void kernel_launch(void* const* d_in, const int* in_sizes, int n_in,
                              void* d_out, int out_size) {
    (void)in_sizes; (void)n_in; (void)out_size;
    const float* x  = (const float*)d_in[0];
    const float* W1 = (const float*)d_in[1];
    const float* b1 = (const float*)d_in[2];
    const float* W2 = (const float*)d_in[3];
    const float* b2 = (const float*)d_in[4];
    const float* W3 = (const float*)d_in[5];
    const float* b3 = (const float*)d_in[6];
    float* out = (float*)d_out;

    const int smem_bytes = (DIM * HID + 14080) * (int)sizeof(float);  // 187392
    static int attr_done = 0;
    if (!attr_done) {
        cudaFuncSetAttribute(k_mega,
                             cudaFuncAttributeMaxDynamicSharedMemorySize, smem_bytes);
        attr_done = 1;
    }

    Dts dts;
    for (int i = 0; i <= NSTEP; ++i) dts.tt[i] = (float)i / 9.0f;

    k_mega<<<GRID, 256, smem_bytes>>>(x, W1, b1, W2, b2, W3, b3, out, dts);
}